// round 2
// baseline (speedup 1.0000x reference)
#include <cuda_runtime.h>

// ---------------------------------------------------------------------------
// DensityGrid: fused opacity/caching + connected-component keep-largest.
// The reference's 288 maxpool-propagation iterations converge to
// "max linear index per 26-connected component" -> computed here with a
// max-based union-find (hook-to-root + full path compression), O(few) rounds.
// Whole working set (~15 MB scratch) is L2-resident.
// R1 fix: old_field input is int32 (jax bool -> harness int32), not bytes.
// ---------------------------------------------------------------------------

#define Gn   96
#define G2n  (Gn * Gn)
#define G3n  (Gn * Gn * Gn)
#define NT   256
#define NB   (G3n / NT)          /* 3456, exact */
#define NB1  ((G3n + 1 + NT - 1) / NT)

// ----- scratch (device globals: no runtime allocation allowed) -------------
__device__ float              g_f0[G3n];
__device__ float              g_f1[G3n];
__device__ unsigned int       g_lab[G3n];
__device__ unsigned char      g_mask[G3n];
__device__ unsigned int       g_cnt[G3n + 1];
__device__ float              g_sum;
__device__ unsigned long long g_winkey;

// ----- tiny init ------------------------------------------------------------
__global__ void k_init() {
    g_sum    = 0.0f;
    g_winkey = 0ull;
}

// ----- elementwise prep: new_cached, out_density, pre-pool field ------------
__global__ void k_prep(const float* __restrict__ dens,
                       const float* __restrict__ cach,
                       float* __restrict__ out) {
    int i = blockIdx.x * NT + threadIdx.x;
    float d  = fmaxf(dens[i], 0.0f);
    float nc = fmaxf(0.8f * cach[i], d);
    out[i]            = 1.0f - expf(-0.01f * d);   // out_density
    out[3 * G3n + i]  = nc;                        // new_cached
    g_f0[i]           = 1.0f - expf(-0.01f * nc);  // pre-pool field
}

// ----- separable 1-D max pool (window 3, pad 1); last pass also reduces sum -
template <int STRIDE, int DIV, bool F0_TO_F1, bool DOSUM>
__global__ void k_pool() {
    const float* in  = F0_TO_F1 ? g_f0 : g_f1;
    float*       out = F0_TO_F1 ? g_f1 : g_f0;
    int i = blockIdx.x * NT + threadIdx.x;
    int c = (i / DIV) % Gn;
    float v = in[i];
    if (c > 0)      v = fmaxf(v, in[i - STRIDE]);
    if (c < Gn - 1) v = fmaxf(v, in[i + STRIDE]);
    out[i] = v;

    if (DOSUM) {
        float s = v;
        #pragma unroll
        for (int off = 16; off > 0; off >>= 1)
            s += __shfl_down_sync(0xffffffffu, s, off);
        __shared__ float sh[NT / 32];
        int lane = threadIdx.x & 31, wid = threadIdx.x >> 5;
        if (lane == 0) sh[wid] = s;
        __syncthreads();
        if (wid == 0) {
            s = (lane < NT / 32) ? sh[lane] : 0.0f;
            #pragma unroll
            for (int off = 4; off > 0; off >>= 1)
                s += __shfl_down_sync(0xffffffffu, s, off);
            if (lane == 0) atomicAdd(&g_sum, s);
        }
    }
}

// ----- mask + label init + histogram clear ----------------------------------
__global__ void k_mask() {
    int i = blockIdx.x * NT + threadIdx.x;
    float thresh = fminf(g_sum * (1.0f / (float)G3n), 0.01f);
    bool m = g_f1[i] > thresh;
    g_mask[i] = m ? 1 : 0;
    g_lab[i]  = m ? (unsigned)(i + 1) : 0u;
    g_cnt[i]  = 0u;
    if (i == 0) g_cnt[G3n] = 0u;
}

// ----- union-find link: hook root to max 26-neighbor label ------------------
__global__ void k_link() {
    int i = blockIdx.x * NT + threadIdx.x;
    if (!g_mask[i]) return;
    unsigned L = g_lab[i];
    unsigned M = L;
    int c2 = i % Gn, c1 = (i / Gn) % Gn, c0 = i / G2n;
    #pragma unroll
    for (int dz = -1; dz <= 1; ++dz) {
        int z = c0 + dz;
        if ((unsigned)z >= (unsigned)Gn) continue;
        #pragma unroll
        for (int dy = -1; dy <= 1; ++dy) {
            int y = c1 + dy;
            if ((unsigned)y >= (unsigned)Gn) continue;
            #pragma unroll
            for (int dx = -1; dx <= 1; ++dx) {
                int x = c2 + dx;
                if ((unsigned)x >= (unsigned)Gn) continue;
                unsigned v = g_lab[(z * Gn + y) * Gn + x];
                M = (v > M) ? v : M;
            }
        }
    }
    if (M > L) atomicMax(&g_lab[L - 1u], M);
}

// ----- full path compression (in-place; monotone-safe under races) ----------
__global__ void k_compress() {
    int i = blockIdx.x * NT + threadIdx.x;
    if (!g_mask[i]) return;
    unsigned w = g_lab[i] - 1u;
    for (;;) {
        unsigned p = g_lab[w];
        if (p == w + 1u) break;
        w = p - 1u;
    }
    g_lab[i] = w + 1u;
}

// ----- warp-aggregated histogram of labels -----------------------------------
__global__ void k_hist() {
    int i = blockIdx.x * NT + threadIdx.x;
    unsigned L = g_mask[i] ? g_lab[i] : 0u;
    unsigned peers = __match_any_sync(0xffffffffu, L);
    int lane   = threadIdx.x & 31;
    int leader = __ffs(peers) - 1;
    if (L != 0u && lane == leader)
        atomicAdd(&g_cnt[L], (unsigned)__popc(peers));
}

// ----- argmax(count), tie -> smallest label ----------------------------------
__global__ void k_argmax() {
    int b = blockIdx.x * NT + threadIdx.x;
    unsigned long long key = 0ull;
    if (b <= G3n) {
        unsigned c = g_cnt[b];
        if (c > 0u)
            key = ((unsigned long long)c << 32) |
                  (unsigned long long)(0xFFFFFFFFu - (unsigned)b);
    }
    #pragma unroll
    for (int off = 16; off > 0; off >>= 1) {
        unsigned long long o = __shfl_down_sync(0xffffffffu, key, off);
        key = (o > key) ? o : key;
    }
    __shared__ unsigned long long sh[NT / 32];
    int lane = threadIdx.x & 31, wid = threadIdx.x >> 5;
    if (lane == 0) sh[wid] = key;
    __syncthreads();
    if (wid == 0) {
        key = (lane < NT / 32) ? sh[lane] : 0ull;
        #pragma unroll
        for (int off = 4; off > 0; off >>= 1) {
            unsigned long long o = __shfl_down_sync(0xffffffffu, key, off);
            key = (o > key) ? o : key;
        }
        if (lane == 0 && key != 0ull) atomicMax(&g_winkey, key);
    }
}

// ----- final outputs: new_field + valid --------------------------------------
__global__ void k_out(const int* __restrict__ oldf,
                      const int* __restrict__ step,
                      float* __restrict__ out) {
    int i = blockIdx.x * NT + threadIdx.x;
    unsigned win = 0xFFFFFFFFu - (unsigned)(g_winkey & 0xFFFFFFFFull);
    bool nf = (g_lab[i] == win);
    out[2 * G3n + i] = nf ? 1.0f : 0.0f;                 // new_field
    int st = step[0];
    bool valid = (st < 500) ? nf : (oldf[i] != 0);
    out[G3n + i] = valid ? 1.0f : 0.0f;                  // valid
}

// ---------------------------------------------------------------------------
extern "C" void kernel_launch(void* const* d_in, const int* in_sizes, int n_in,
                              void* d_out, int out_size) {
    const float* dens = (const float*)d_in[0];
    const float* cach = (const float*)d_in[1];
    const int*   oldf = (const int*)d_in[2];
    const int*   step = (const int*)d_in[3];
    float*       out  = (float*)d_out;

    k_init<<<1, 1>>>();
    k_prep<<<NB, NT>>>(dens, cach, out);

    // separable 3x3x3 max pool: axis2 (stride 1) -> axis1 (stride G) -> axis0
    k_pool<1,    1,    true,  false><<<NB, NT>>>();
    k_pool<Gn,   Gn,   false, false><<<NB, NT>>>();
    k_pool<G2n,  G2n,  true,  true ><<<NB, NT>>>();

    k_mask<<<NB, NT>>>();

    // max-union-find: (link + compress) rounds; converges in ~2 for this data
    for (int r = 0; r < 5; ++r) {
        k_link<<<NB, NT>>>();
        k_compress<<<NB, NT>>>();
    }

    k_hist<<<NB, NT>>>();
    k_argmax<<<NB1, NT>>>();
    k_out<<<NB, NT>>>(oldf, step, out);
}